// round 9
// baseline (speedup 1.0000x reference)
#include <cuda_runtime.h>
#include <math.h>

// ---------------------------------------------------------------------------
// Matern kernel matrix via tabulated L(x) = log2(C * x^nu * K_nu(x)).
// Kernel 1 builds a 1025-entry table over x in [0,96].
// Kernel 2: 32x32 tiles (1024 blocks -> ~7 CTAs/SM for latency hiding),
// 256 threads, 2x2 STRIDED micro-tile (i = ty+16r, j = tx+16c): b-operand
// LDS.128 is bank-conflict-free with the 36-word row stride, a-operand is a
// warp broadcast. Tiles pre-scaled by fac*INVDX so sqrt.approx gives the
// table coordinate directly; norms fused into the load phase via shfl.
// ---------------------------------------------------------------------------

#define TBL_N    1024
#define TBL_XMAX 96.0f
#define TBL_DX   (TBL_XMAX / TBL_N)
#define TBL_INVDX ((float)TBL_N / TBL_XMAX)

#define NQT 48
#define HQT (6.0f / (NQT - 1))
#define LOG2E 1.44269504088896340736f

__device__ float2 g_tbl[TBL_N + 2];   // {L_k, L_{k+1}}
__device__ float  g_fac;              // sqrt(2 nu) / lengthscale
__device__ float  g_var;              // variance

__device__ __forceinline__ float ex2f(float x) {
    float r; asm("ex2.approx.ftz.f32 %0, %1;" : "=f"(r) : "f"(x)); return r;
}
__device__ __forceinline__ float lg2f(float x) {
    float r; asm("lg2.approx.f32 %0, %1;" : "=f"(r) : "f"(x)); return r;
}
__device__ __forceinline__ float sqrt_approx(float x) {
    float r; asm("sqrt.approx.ftz.f32 %0, %1;" : "=f"(r) : "f"(x)); return r;
}

// --- kernel 1: table build (8 lanes per entry, 32 entries per block) --------
__global__ __launch_bounds__(256) void build_table(const float* __restrict__ nu_p,
                                                   const float* __restrict__ lv_p,
                                                   const float* __restrict__ ll_p) {
    __shared__ float s_log2C, s_nu;
    if (threadIdx.x == 0) {
        float nu = nu_p[0];
        s_nu = nu;
        s_log2C = lv_p[0] * LOG2E + (1.f - nu) - lgammaf(nu) * LOG2E;
        if (blockIdx.x == 0) {
            g_fac = sqrtf(2.f * nu) * __expf(-ll_p[0]);
            g_var = __expf(lv_p[0]);
        }
    }
    __syncthreads();

    const float nu = s_nu;
    const int k    = blockIdx.x * 32 + (threadIdx.x >> 3);
    const int lane = threadIdx.x & 7;
    const float x  = TBL_DX * (float)k;

    float S = 0.f;
#pragma unroll
    for (int m = 0; m < 6; m++) {
        int q   = lane + 8 * m;
        float t = HQT * (float)q;
        float w = (q == 0 || q == NQT - 1) ? 0.5f * HQT : HQT;
        float a = (coshf(t) - 1.f) * LOG2E;
        S += (w * coshf(nu * t)) * ex2f(-x * a);
    }
    S += __shfl_xor_sync(0xffffffffu, S, 1);
    S += __shfl_xor_sync(0xffffffffu, S, 2);
    S += __shfl_xor_sync(0xffffffffu, S, 4);

    if (lane == 0 && k <= TBL_N) {
        float L = s_log2C + nu * lg2f(x) - x * LOG2E + lg2f(S);
        L = fmaxf(L, -150.f);
        g_tbl[k].x = L;
        if (k > 0) g_tbl[k - 1].y = L;
    }
}

// --- kernel 2: 32x32 tiles, 2x2 strided micro-tile ---------------------------
__global__ __launch_bounds__(256) void matern_main(const float* __restrict__ X,
                                                   float* __restrict__ out,
                                                   int N) {
    __shared__ float sxi[32][36];      // row stride 36 floats (16B aligned)
    __shared__ float sxj[32][36];
    __shared__ float sni[32], snj[32];

    const int tid = threadIdx.x;
    const int tx = tid & 15, ty = tid >> 4;
    const int i0 = blockIdx.y * 32, j0 = blockIdx.x * 32;

    const float scale = g_fac * TBL_INVDX;   // uniform broadcast

    // load + scale + fused norm reduction (8 lanes per row)
    {
        const float4* Xi = (const float4*)(X + i0 * 32);
        const float4* Xj = (const float4*)(X + j0 * 32);
        int r = tid >> 3, k = tid & 7;
        float4 vi = Xi[tid];
        float4 vj = Xj[tid];
        vi.x *= scale; vi.y *= scale; vi.z *= scale; vi.w *= scale;
        vj.x *= scale; vj.y *= scale; vj.z *= scale; vj.w *= scale;
        *(float4*)&sxi[r][4 * k] = vi;
        *(float4*)&sxj[r][4 * k] = vj;

        float pi = fmaf(vi.x, vi.x, fmaf(vi.y, vi.y, fmaf(vi.z, vi.z, vi.w * vi.w)));
        float pj = fmaf(vj.x, vj.x, fmaf(vj.y, vj.y, fmaf(vj.z, vj.z, vj.w * vj.w)));
        pi += __shfl_xor_sync(0xffffffffu, pi, 1);
        pj += __shfl_xor_sync(0xffffffffu, pj, 1);
        pi += __shfl_xor_sync(0xffffffffu, pi, 2);
        pj += __shfl_xor_sync(0xffffffffu, pj, 2);
        pi += __shfl_xor_sync(0xffffffffu, pi, 4);
        pj += __shfl_xor_sync(0xffffffffu, pj, 4);
        if (k == 0) { sni[r] = pi; snj[r] = pj; }
    }
    __syncthreads();

    // 2x2 strided micro-tile: i = ty + 16r, j = tx + 16c
    float acc[2][2] = {{0.f, 0.f}, {0.f, 0.f}};
#pragma unroll
    for (int kc = 0; kc < 8; kc++) {
        float4 a0 = *(const float4*)&sxi[ty][kc * 4];
        float4 a1 = *(const float4*)&sxi[ty + 16][kc * 4];
        float4 b0 = *(const float4*)&sxj[tx][kc * 4];
        float4 b1 = *(const float4*)&sxj[tx + 16][kc * 4];
        acc[0][0] = fmaf(a0.x, b0.x, acc[0][0]); acc[0][0] = fmaf(a0.y, b0.y, acc[0][0]);
        acc[0][0] = fmaf(a0.z, b0.z, acc[0][0]); acc[0][0] = fmaf(a0.w, b0.w, acc[0][0]);
        acc[0][1] = fmaf(a0.x, b1.x, acc[0][1]); acc[0][1] = fmaf(a0.y, b1.y, acc[0][1]);
        acc[0][1] = fmaf(a0.z, b1.z, acc[0][1]); acc[0][1] = fmaf(a0.w, b1.w, acc[0][1]);
        acc[1][0] = fmaf(a1.x, b0.x, acc[1][0]); acc[1][0] = fmaf(a1.y, b0.y, acc[1][0]);
        acc[1][0] = fmaf(a1.z, b0.z, acc[1][0]); acc[1][0] = fmaf(a1.w, b0.w, acc[1][0]);
        acc[1][1] = fmaf(a1.x, b1.x, acc[1][1]); acc[1][1] = fmaf(a1.y, b1.y, acc[1][1]);
        acc[1][1] = fmaf(a1.z, b1.z, acc[1][1]); acc[1][1] = fmaf(a1.w, b1.w, acc[1][1]);
    }

    const float var_s = g_var;
    float ni[2] = {sni[ty], sni[ty + 16]};
    float nj[2] = {snj[tx], snj[tx + 16]};

    const bool diagblk = (blockIdx.x == blockIdx.y);

#pragma unroll
    for (int r = 0; r < 2; r++) {
        const int i = i0 + ty + 16 * r;
#pragma unroll
        for (int c = 0; c < 2; c++) {
            const int j = j0 + tx + 16 * c;
            float sq = fmaxf(fmaf(-2.f, acc[r][c], ni[r] + nj[c]), 0.f);
            float u  = fminf(sqrt_approx(sq), (float)TBL_N - 0.001f);
            int   kk = (int)u;
            float f  = u - (float)kk;
            float2 Lp = __ldg(&g_tbl[kk]);
            float val = ex2f(fmaf(f, Lp.y - Lp.x, Lp.x));
            if (diagblk && i == j) val = var_s;
            out[i * N + j] = val;
        }
    }
}

extern "C" void kernel_launch(void* const* d_in, const int* in_sizes, int n_in,
                              void* d_out, int out_size) {
    const float* X  = (const float*)d_in[0];
    const float* nu = (const float*)d_in[1];
    const float* lv = (const float*)d_in[2];
    const float* ll = (const float*)d_in[3];
    float* out = (float*)d_out;
    const int N = in_sizes[0] / 32;   // 1024

    build_table<<<(TBL_N + 1 + 31) / 32, 256>>>(nu, lv, ll);

    dim3 grid(N / 32, N / 32), block(256);
    matern_main<<<grid, block>>>(X, out, N);
}

// round 10
// speedup vs baseline: 1.2107x; 1.2107x over previous
#include <cuda_runtime.h>
#include <math.h>

// ---------------------------------------------------------------------------
// Matern kernel matrix via tabulated L(x) = log2(C * x^nu * K_nu(x)).
// Kernel 1 builds a 1025-entry table over x in [0,96].
// Kernel 2: 64x64 tiles, 512 threads (16 warps -> ~2 CTAs / 32 warps per SM),
// 2x4 strided micro-tile (i = ty+32r, j = tx+16c): conflict-free b-operand
// LDS.128, warp-broadcast a-operand. Tiles pre-scaled by fac*INVDX so
// sqrt.approx gives the table coordinate directly; norms fused into loads.
// ---------------------------------------------------------------------------

#define TBL_N    1024
#define TBL_XMAX 96.0f
#define TBL_DX   (TBL_XMAX / TBL_N)
#define TBL_INVDX ((float)TBL_N / TBL_XMAX)

#define NQT 48
#define HQT (6.0f / (NQT - 1))
#define LOG2E 1.44269504088896340736f

__device__ float2 g_tbl[TBL_N + 2];   // {L_k, L_{k+1}}
__device__ float  g_fac;              // sqrt(2 nu) / lengthscale
__device__ float  g_var;              // variance

__device__ __forceinline__ float ex2f(float x) {
    float r; asm("ex2.approx.ftz.f32 %0, %1;" : "=f"(r) : "f"(x)); return r;
}
__device__ __forceinline__ float lg2f(float x) {
    float r; asm("lg2.approx.f32 %0, %1;" : "=f"(r) : "f"(x)); return r;
}
__device__ __forceinline__ float sqrt_approx(float x) {
    float r; asm("sqrt.approx.ftz.f32 %0, %1;" : "=f"(r) : "f"(x)); return r;
}

// --- kernel 1: table build (8 lanes per entry, 32 entries per block) --------
__global__ __launch_bounds__(256) void build_table(const float* __restrict__ nu_p,
                                                   const float* __restrict__ lv_p,
                                                   const float* __restrict__ ll_p) {
    __shared__ float s_log2C, s_nu;
    if (threadIdx.x == 0) {
        float nu = nu_p[0];
        s_nu = nu;
        s_log2C = lv_p[0] * LOG2E + (1.f - nu) - lgammaf(nu) * LOG2E;
        if (blockIdx.x == 0) {
            g_fac = sqrtf(2.f * nu) * __expf(-ll_p[0]);
            g_var = __expf(lv_p[0]);
        }
    }
    __syncthreads();

    const float nu = s_nu;
    const int k    = blockIdx.x * 32 + (threadIdx.x >> 3);
    const int lane = threadIdx.x & 7;
    const float x  = TBL_DX * (float)k;

    float S = 0.f;
#pragma unroll
    for (int m = 0; m < 6; m++) {
        int q   = lane + 8 * m;
        float t = HQT * (float)q;
        float w = (q == 0 || q == NQT - 1) ? 0.5f * HQT : HQT;
        float a = (coshf(t) - 1.f) * LOG2E;
        S += (w * coshf(nu * t)) * ex2f(-x * a);
    }
    S += __shfl_xor_sync(0xffffffffu, S, 1);
    S += __shfl_xor_sync(0xffffffffu, S, 2);
    S += __shfl_xor_sync(0xffffffffu, S, 4);

    if (lane == 0 && k <= TBL_N) {
        float L = s_log2C + nu * lg2f(x) - x * LOG2E + lg2f(S);
        L = fmaxf(L, -150.f);
        g_tbl[k].x = L;
        if (k > 0) g_tbl[k - 1].y = L;
    }
}

// --- kernel 2: 64x64 tiles, 512 threads, 2x4 strided micro-tile --------------
__global__ __launch_bounds__(512) void matern_main(const float* __restrict__ X,
                                                   float* __restrict__ out,
                                                   int N) {
    __shared__ float sxi[64][36];
    __shared__ float sxj[64][36];
    __shared__ float sni[64], snj[64];

    const int tid = threadIdx.x;
    const int tx = tid & 15, ty = tid >> 4;     // tx 0..15, ty 0..31
    const int i0 = blockIdx.y * 64, j0 = blockIdx.x * 64;

    const float scale = g_fac * TBL_INVDX;      // uniform broadcast

    // load + scale + fused norm reduction (8 lanes per row); 512 float4 total
    {
        const float4* Xi = (const float4*)(X + i0 * 32);
        const float4* Xj = (const float4*)(X + j0 * 32);
        int r = tid >> 3, k = tid & 7;          // covers all 64 rows x 8 chunks
        float4 vi = Xi[tid];
        float4 vj = Xj[tid];
        vi.x *= scale; vi.y *= scale; vi.z *= scale; vi.w *= scale;
        vj.x *= scale; vj.y *= scale; vj.z *= scale; vj.w *= scale;
        *(float4*)&sxi[r][4 * k] = vi;
        *(float4*)&sxj[r][4 * k] = vj;

        float pi = fmaf(vi.x, vi.x, fmaf(vi.y, vi.y, fmaf(vi.z, vi.z, vi.w * vi.w)));
        float pj = fmaf(vj.x, vj.x, fmaf(vj.y, vj.y, fmaf(vj.z, vj.z, vj.w * vj.w)));
        pi += __shfl_xor_sync(0xffffffffu, pi, 1);
        pj += __shfl_xor_sync(0xffffffffu, pj, 1);
        pi += __shfl_xor_sync(0xffffffffu, pi, 2);
        pj += __shfl_xor_sync(0xffffffffu, pj, 2);
        pi += __shfl_xor_sync(0xffffffffu, pi, 4);
        pj += __shfl_xor_sync(0xffffffffu, pj, 4);
        if (k == 0) { sni[r] = pi; snj[r] = pj; }
    }
    __syncthreads();

    // 2x4 micro-tile: rows i = ty + 32r, cols j = tx + 16c
    float acc[2][4];
#pragma unroll
    for (int r = 0; r < 2; r++)
#pragma unroll
        for (int c = 0; c < 4; c++) acc[r][c] = 0.f;

#pragma unroll
    for (int kc = 0; kc < 8; kc++) {
        float4 a[2], b[4];
#pragma unroll
        for (int r = 0; r < 2; r++) a[r] = *(const float4*)&sxi[ty + 32 * r][kc * 4];
#pragma unroll
        for (int c = 0; c < 4; c++) b[c] = *(const float4*)&sxj[tx + 16 * c][kc * 4];
#pragma unroll
        for (int r = 0; r < 2; r++)
#pragma unroll
            for (int c = 0; c < 4; c++) {
                acc[r][c] = fmaf(a[r].x, b[c].x, acc[r][c]);
                acc[r][c] = fmaf(a[r].y, b[c].y, acc[r][c]);
                acc[r][c] = fmaf(a[r].z, b[c].z, acc[r][c]);
                acc[r][c] = fmaf(a[r].w, b[c].w, acc[r][c]);
            }
    }

    const float var_s = g_var;
    float ni[2] = {sni[ty], sni[ty + 32]};
    float nj[4];
#pragma unroll
    for (int c = 0; c < 4; c++) nj[c] = snj[tx + 16 * c];

    const bool diagblk = (blockIdx.x == blockIdx.y);

#pragma unroll
    for (int r = 0; r < 2; r++) {
        const int i = i0 + ty + 32 * r;
#pragma unroll
        for (int c = 0; c < 4; c++) {
            const int j = j0 + tx + 16 * c;
            float sq = fmaxf(fmaf(-2.f, acc[r][c], ni[r] + nj[c]), 0.f);
            float u  = fminf(sqrt_approx(sq), (float)TBL_N - 0.001f);
            int   kk = (int)u;
            float f  = u - (float)kk;
            float2 Lp = __ldg(&g_tbl[kk]);
            float val = ex2f(fmaf(f, Lp.y - Lp.x, Lp.x));
            if (diagblk && i == j) val = var_s;
            out[i * N + j] = val;
        }
    }
}

extern "C" void kernel_launch(void* const* d_in, const int* in_sizes, int n_in,
                              void* d_out, int out_size) {
    const float* X  = (const float*)d_in[0];
    const float* nu = (const float*)d_in[1];
    const float* lv = (const float*)d_in[2];
    const float* ll = (const float*)d_in[3];
    float* out = (float*)d_out;
    const int N = in_sizes[0] / 32;   // 1024

    build_table<<<(TBL_N + 1 + 31) / 32, 256>>>(nu, lv, ll);

    dim3 grid(N / 64, N / 64), block(512);
    matern_main<<<grid, block>>>(X, out, N);
}

// round 11
// speedup vs baseline: 1.2216x; 1.0090x over previous
#include <cuda_runtime.h>
#include <math.h>

// ---------------------------------------------------------------------------
// Matern kernel matrix via tabulated L(x) = log2(C * x^nu * K_nu(x)).
// Kernel 1 builds a 1025-entry table over x in [0,96].
// Kernel 2: 64x64 tiles, 256 threads, 4x4 strided micro-tile (conflict-free
// LDS), table copied to SMEM: the per-lane scattered table lookup was the
// binder (random LDG.64 into 8KB -> ~28 L1tex wavefronts per warp-lookup;
// scattered LDS.64 is ~4-8 cycles). Tiles pre-scaled by fac*INVDX so
// sqrt.approx gives the table coordinate directly; norms fused into loads.
// ---------------------------------------------------------------------------

#define TBL_N    1024
#define TBL_XMAX 96.0f
#define TBL_DX   (TBL_XMAX / TBL_N)
#define TBL_INVDX ((float)TBL_N / TBL_XMAX)

#define NQT 48
#define HQT (6.0f / (NQT - 1))
#define LOG2E 1.44269504088896340736f

__device__ float2 g_tbl[TBL_N + 2];   // {L_k, L_{k+1}}
__device__ float  g_fac;              // sqrt(2 nu) / lengthscale
__device__ float  g_var;              // variance

__device__ __forceinline__ float ex2f(float x) {
    float r; asm("ex2.approx.ftz.f32 %0, %1;" : "=f"(r) : "f"(x)); return r;
}
__device__ __forceinline__ float lg2f(float x) {
    float r; asm("lg2.approx.f32 %0, %1;" : "=f"(r) : "f"(x)); return r;
}
__device__ __forceinline__ float sqrt_approx(float x) {
    float r; asm("sqrt.approx.ftz.f32 %0, %1;" : "=f"(r) : "f"(x)); return r;
}

// --- kernel 1: table build (8 lanes per entry, 32 entries per block) --------
__global__ __launch_bounds__(256) void build_table(const float* __restrict__ nu_p,
                                                   const float* __restrict__ lv_p,
                                                   const float* __restrict__ ll_p) {
    __shared__ float s_log2C, s_nu;
    if (threadIdx.x == 0) {
        float nu = nu_p[0];
        s_nu = nu;
        s_log2C = lv_p[0] * LOG2E + (1.f - nu) - lgammaf(nu) * LOG2E;
        if (blockIdx.x == 0) {
            g_fac = sqrtf(2.f * nu) * __expf(-ll_p[0]);
            g_var = __expf(lv_p[0]);
        }
    }
    __syncthreads();

    const float nu = s_nu;
    const int k    = blockIdx.x * 32 + (threadIdx.x >> 3);
    const int lane = threadIdx.x & 7;
    const float x  = TBL_DX * (float)k;

    float S = 0.f;
#pragma unroll
    for (int m = 0; m < 6; m++) {
        int q   = lane + 8 * m;
        float t = HQT * (float)q;
        float w = (q == 0 || q == NQT - 1) ? 0.5f * HQT : HQT;
        float a = (coshf(t) - 1.f) * LOG2E;
        S += (w * coshf(nu * t)) * ex2f(-x * a);
    }
    S += __shfl_xor_sync(0xffffffffu, S, 1);
    S += __shfl_xor_sync(0xffffffffu, S, 2);
    S += __shfl_xor_sync(0xffffffffu, S, 4);

    if (lane == 0 && k <= TBL_N) {
        float L = s_log2C + nu * lg2f(x) - x * LOG2E + lg2f(S);
        L = fmaxf(L, -150.f);
        g_tbl[k].x = L;
        if (k > 0) g_tbl[k - 1].y = L;
    }
}

// --- kernel 2: 64x64 tiles, 4x4 strided micro, smem table --------------------
__global__ __launch_bounds__(256) void matern_main(const float* __restrict__ X,
                                                   float* __restrict__ out,
                                                   int N) {
    __shared__ float  sxi[64][36];
    __shared__ float  sxj[64][36];
    __shared__ float  sni[64], snj[64];
    __shared__ float2 stbl[TBL_N + 1];

    const int tid = threadIdx.x;
    const int tx = tid & 15, ty = tid >> 4;
    const int i0 = blockIdx.y * 64, j0 = blockIdx.x * 64;

    // table copy FIRST (coalesced LDG.128; overlaps with tile loads below)
    {
        const float4* gt = (const float4*)g_tbl;   // 1025 float2 = 512.5 float4
#pragma unroll
        for (int m = 0; m < 2; m++) {
            int idx = m * 256 + tid;               // 0..511
            *(float4*)&stbl[idx * 2] = gt[idx];
        }
        if (tid == 0) stbl[TBL_N] = g_tbl[TBL_N];
    }

    const float scale = g_fac * TBL_INVDX;   // uniform broadcast

    // tile loads + scale + fused norm reduction (8 lanes per row)
    {
        const float4* Xi = (const float4*)(X + i0 * 32);
        const float4* Xj = (const float4*)(X + j0 * 32);
        const int k = tid & 7;
#pragma unroll
        for (int m = 0; m < 2; m++) {
            int idx = m * 256 + tid;          // 0..511
            int r = idx >> 3;
            float4 vi = Xi[idx];
            float4 vj = Xj[idx];
            vi.x *= scale; vi.y *= scale; vi.z *= scale; vi.w *= scale;
            vj.x *= scale; vj.y *= scale; vj.z *= scale; vj.w *= scale;
            *(float4*)&sxi[r][4 * k] = vi;
            *(float4*)&sxj[r][4 * k] = vj;
            float pi = fmaf(vi.x, vi.x, fmaf(vi.y, vi.y, fmaf(vi.z, vi.z, vi.w * vi.w)));
            float pj = fmaf(vj.x, vj.x, fmaf(vj.y, vj.y, fmaf(vj.z, vj.z, vj.w * vj.w)));
            pi += __shfl_xor_sync(0xffffffffu, pi, 1);
            pj += __shfl_xor_sync(0xffffffffu, pj, 1);
            pi += __shfl_xor_sync(0xffffffffu, pi, 2);
            pj += __shfl_xor_sync(0xffffffffu, pj, 2);
            pi += __shfl_xor_sync(0xffffffffu, pi, 4);
            pj += __shfl_xor_sync(0xffffffffu, pj, 4);
            if (k == 0) { sni[r] = pi; snj[r] = pj; }
        }
    }
    __syncthreads();

    // 4x4 micro-tile: rows i = ty*4 + r (contiguous), cols j = tx + 16*c
    float acc[4][4];
#pragma unroll
    for (int r = 0; r < 4; r++)
#pragma unroll
        for (int c = 0; c < 4; c++) acc[r][c] = 0.f;

#pragma unroll
    for (int kc = 0; kc < 8; kc++) {
        float4 a[4], b[4];
#pragma unroll
        for (int r = 0; r < 4; r++) a[r] = *(const float4*)&sxi[ty * 4 + r][kc * 4];
#pragma unroll
        for (int c = 0; c < 4; c++) b[c] = *(const float4*)&sxj[tx + 16 * c][kc * 4];
#pragma unroll
        for (int r = 0; r < 4; r++)
#pragma unroll
            for (int c = 0; c < 4; c++) {
                acc[r][c] = fmaf(a[r].x, b[c].x, acc[r][c]);
                acc[r][c] = fmaf(a[r].y, b[c].y, acc[r][c]);
                acc[r][c] = fmaf(a[r].z, b[c].z, acc[r][c]);
                acc[r][c] = fmaf(a[r].w, b[c].w, acc[r][c]);
            }
    }

    const float var_s = g_var;
    float ni[4], nj[4];
#pragma unroll
    for (int r = 0; r < 4; r++) ni[r] = sni[ty * 4 + r];
#pragma unroll
    for (int c = 0; c < 4; c++) nj[c] = snj[tx + 16 * c];

    const bool diagblk = (blockIdx.x == blockIdx.y);

#pragma unroll
    for (int r = 0; r < 4; r++) {
        const int i = i0 + ty * 4 + r;
#pragma unroll
        for (int c = 0; c < 4; c++) {
            const int j = j0 + tx + 16 * c;
            float sq = fmaxf(fmaf(-2.f, acc[r][c], ni[r] + nj[c]), 0.f);
            float u  = fminf(sqrt_approx(sq), (float)TBL_N - 0.001f);
            int   kk = (int)u;
            float f  = u - (float)kk;
            float2 Lp = stbl[kk];
            float val = ex2f(fmaf(f, Lp.y - Lp.x, Lp.x));
            if (diagblk && i == j) val = var_s;
            out[i * N + j] = val;
        }
    }
}

extern "C" void kernel_launch(void* const* d_in, const int* in_sizes, int n_in,
                              void* d_out, int out_size) {
    const float* X  = (const float*)d_in[0];
    const float* nu = (const float*)d_in[1];
    const float* lv = (const float*)d_in[2];
    const float* ll = (const float*)d_in[3];
    float* out = (float*)d_out;
    const int N = in_sizes[0] / 32;   // 1024

    build_table<<<(TBL_N + 1 + 31) / 32, 256>>>(nu, lv, ll);

    dim3 grid(N / 64, N / 64), block(256);
    matern_main<<<grid, block>>>(X, out, N);
}